// round 14
// baseline (speedup 1.0000x reference)
#include <cuda_runtime.h>
#include <cstdint>

#define NROWS 131072
#define DIM   192
#define KC    256     // concat(local, global) prototype count
#define MPROT 128
#define INV_T 20.0f   // 1 / 0.05

// ---------------- device scratch (allocation-free: module globals) ----------
__device__ float  g_E[(size_t)NROWS * KC];   // exp(sim/T), 128 MB
__device__ float  g_pnT[DIM * KC];           // normalized protos, transposed [k][j]
__device__ double g_colsum[3][KC];           // sinkhorn colsum accumulators
__device__ float  g_C[4][KC];                // column factors (C[1..3] used)
__device__ float  g_hgate[MPROT * DIM];      // 0.5 * GLU(globalProto) table
__device__ int    g_lastIdx[MPROT];          // last row assigned per local proto

// ---------------- init: zero accumulators every launch ----------------------
__global__ void k_init() {
    int t = threadIdx.x;
    if (t < MPROT) g_lastIdx[t] = -1;
    for (int i = t; i < 3 * KC; i += blockDim.x)
        ((double*)g_colsum)[i] = 0.0;
}

// ---------------- normalize prototypes, store transposed --------------------
__global__ void k_protos(const float* __restrict__ lp, const float* __restrict__ gp) {
    int j = threadIdx.x;  // 0..255
    const float* src = (j < MPROT) ? (lp + j * DIM) : (gp + (j - MPROT) * DIM);
    float ss = 0.f;
    for (int k = 0; k < DIM; k++) { float v = src[k]; ss += v * v; }
    float inv = rsqrtf(fmaxf(ss, 1e-12f));
    for (int k = 0; k < DIM; k++) g_pnT[k * KC + j] = src[k] * inv;
}

// ---------------- GEMM: sim = x @ pnT, E = exp(sim * invx * 20) -------------
// Block: 64 rows x 256 cols, 256 threads. Thread tile 8 rows x 8 cols.
// A stored PRE-DUPLICATED as u64 {a,a} -> inner loop has no packing movs:
//   per k: 4 LDS.64 (b pairs) + 8 LDS.64 (a, warp-broadcast) + 32 FFMA2.
// Row ||x||^2 fused into the A-load phase (replaces k_xnorm).
// Epilogue performs sinkhorn iteration 0 (uniform C0 dropped — argmax-neutral):
//   colsum[0]_j += E_ij / rowsum_i.
__global__ __launch_bounds__(256, 2) void k_gemm(const float* __restrict__ x) {
    __shared__ unsigned long long As2[64][32];   // {a,a} pairs, 16 KB
    __shared__ float Bs[32][KC];                 // 32 KB (reused for reduction)
    __shared__ float normp[64][8];               // ||x||^2 partials
    __shared__ float sinvx[64];                  // 1/||x|| per row
    int rowBase = blockIdx.x * 64;
    int tid = threadIdx.x;
    int ty = tid >> 5;   // warp -> 8-row group (a loads are warp-uniform)
    int tx = tid & 31;   // lane -> column pairs

    unsigned long long acc[8][4];
#pragma unroll
    for (int i = 0; i < 8; i++)
#pragma unroll
        for (int j = 0; j < 4; j++) acc[i][j] = 0ull;

    int ar = tid >> 3;         // A row (0..31); +32 for second half
    int ac = (tid & 7) * 4;    // A col within chunk
    float ss0 = 0.f, ss1 = 0.f;

    for (int kb = 0; kb < DIM; kb += 32) {
        // A tile 64x32 as duplicated u64 pairs; accumulate ||x||^2 partials
#pragma unroll
        for (int u = 0; u < 2; u++) {
            int r = ar + u * 32;
            float4 v = *(const float4*)&x[(size_t)(rowBase + r) * DIM + kb + ac];
            float d = v.x * v.x + v.y * v.y + v.z * v.z + v.w * v.w;
            if (u == 0) ss0 += d; else ss1 += d;
            unsigned long long p0, p1, p2, p3;
            asm("mov.b64 %0, {%1, %1};" : "=l"(p0) : "f"(v.x));
            asm("mov.b64 %0, {%1, %1};" : "=l"(p1) : "f"(v.y));
            asm("mov.b64 %0, {%1, %1};" : "=l"(p2) : "f"(v.z));
            asm("mov.b64 %0, {%1, %1};" : "=l"(p3) : "f"(v.w));
            As2[r][ac + 0] = p0; As2[r][ac + 1] = p1;
            As2[r][ac + 2] = p2; As2[r][ac + 3] = p3;
        }
        // B tile 32x256: 2048 float4, 8 per thread (coalesced, conflict-free)
#pragma unroll
        for (int u = 0; u < 8; u++) {
            int f = tid + u * 256;
            int kk = f >> 6, c = (f & 63) * 4;
            *(float4*)&Bs[kk][c] = *(const float4*)&g_pnT[(kb + kk) * KC + c];
        }
        __syncthreads();
#pragma unroll
        for (int k = 0; k < 32; k++) {
            unsigned long long b[4];
#pragma unroll
            for (int j = 0; j < 4; j++)
                b[j] = *(const unsigned long long*)&Bs[k][64 * j + 2 * tx];
#pragma unroll
            for (int i = 0; i < 8; i++) {
                unsigned long long a2 = As2[ty * 8 + i][k];  // broadcast LDS.64
#pragma unroll
                for (int j = 0; j < 4; j++)
                    asm("fma.rn.f32x2 %0, %1, %2, %0;"
                        : "+l"(acc[i][j]) : "l"(a2), "l"(b[j]));
            }
        }
        __syncthreads();
    }

    // finalize 1/||x|| per row (8 partials per row)
    normp[ar][tid & 7] = ss0;
    normp[ar + 32][tid & 7] = ss1;
    __syncthreads();
    if (tid < 64) {
        float s = 0.f;
#pragma unroll
        for (int j = 0; j < 8; j++) s += normp[tid][j];
        sinvx[tid] = rsqrtf(fmaxf(s, 1e-12f));
    }
    __syncthreads();

    // epilogue: E = exp(20*sim/||x||), store E, accumulate colsum[0] += E/rowsum
    float colAcc[8] = {0, 0, 0, 0, 0, 0, 0, 0};
#pragma unroll
    for (int i = 0; i < 8; i++) {
        int row = rowBase + ty * 8 + i;
        float sc = INV_T * sinvx[ty * 8 + i];
        float ev[8];
        float rsum = 0.f;
#pragma unroll
        for (int j = 0; j < 4; j++) {
            float lo, hi;
            asm("mov.b64 {%0, %1}, %2;" : "=f"(lo), "=f"(hi) : "l"(acc[i][j]));
            float e0 = __expf(sc * lo);
            float e1 = __expf(sc * hi);
            ev[2 * j] = e0; ev[2 * j + 1] = e1;
            rsum += e0 + e1;
            int c = 64 * j + 2 * tx;
            *(float2*)&g_E[(size_t)row * KC + c] = make_float2(e0, e1);
        }
#pragma unroll
        for (int o = 16; o; o >>= 1) rsum += __shfl_xor_sync(0xffffffffu, rsum, o);
        float R = 1.0f / rsum;   // warp holds the full row -> exact rowsum
#pragma unroll
        for (int j = 0; j < 8; j++) colAcc[j] = fmaf(ev[j], R, colAcc[j]);
    }

    // block-reduce colAcc into g_colsum[0] (reuse Bs: mainloop done with it)
    double (*wsum)[KC] = (double(*)[KC])Bs;
#pragma unroll
    for (int j = 0; j < 4; j++) {
        wsum[ty][64 * j + 2 * tx]     = (double)colAcc[2 * j];
        wsum[ty][64 * j + 2 * tx + 1] = (double)colAcc[2 * j + 1];
    }
    __syncthreads();
    double s = 0.0;
#pragma unroll
    for (int ww = 0; ww < 8; ww++) s += wsum[ww][tid];
    atomicAdd(&g_colsum[0][tid], s);
}

// ---------------- finalize column factors: C[t+1][j] = 1/(256*colsum[t][j]) --
__global__ void k_setC(int t) {
    int j = threadIdx.x;
    g_C[t + 1][j] = (float)(1.0 / (256.0 * g_colsum[t][j]));
}

// ---------------- one sinkhorn iteration: one pass over E --------------------
// R_i = 1/(N * sum_j E_ij C_j);  colsum_j += sum_i E_ij R_i   (double accum)
__global__ __launch_bounds__(256) void k_pass(int iter) {
    __shared__ double wsum[8][KC];
    int tid = threadIdx.x, w = tid >> 5, lane = tid & 31;
    const float* C = g_C[iter];
    float cl[8];
#pragma unroll
    for (int i = 0; i < 8; i++) cl[i] = C[lane * 8 + i];
    float colAcc[8] = {0, 0, 0, 0, 0, 0, 0, 0};
    int row0 = blockIdx.x * 64 + w * 8;
#pragma unroll
    for (int r = 0; r < 8; r++) {
        const float4* p = (const float4*)&g_E[(size_t)(row0 + r) * KC + lane * 8];
        float4 e0 = p[0], e1 = p[1];
        float e[8] = {e0.x, e0.y, e0.z, e0.w, e1.x, e1.y, e1.z, e1.w};
        float rd = 0.f;
#pragma unroll
        for (int i = 0; i < 8; i++) rd = fmaf(e[i], cl[i], rd);
#pragma unroll
        for (int o = 16; o; o >>= 1) rd += __shfl_xor_sync(0xffffffffu, rd, o);
        float R = 1.0f / (131072.0f * rd);
#pragma unroll
        for (int i = 0; i < 8; i++) colAcc[i] = fmaf(e[i], R, colAcc[i]);
    }
#pragma unroll
    for (int i = 0; i < 8; i++) wsum[w][lane * 8 + i] = (double)colAcc[i];
    __syncthreads();
    double s = 0.0;
#pragma unroll
    for (int ww = 0; ww < 8; ww++) s += wsum[ww][tid];
    atomicAdd(&g_colsum[iter][tid], s);
}

// ---------------- 0.5*GLU table for the 128 global prototypes ----------------
__global__ void k_glu(const float* __restrict__ gp, const float* __restrict__ W,
                      const float* __restrict__ bias) {
    __shared__ float gpr[DIM];
    __shared__ float lin[2 * DIM];
    int m = blockIdx.x, t = threadIdx.x;     // 384 threads
    if (t < DIM) gpr[t] = gp[m * DIM + t];
    __syncthreads();
    float s = bias[t];
    for (int k = 0; k < DIM; k++) s = fmaf(gpr[k], W[(size_t)k * 2 * DIM + t], s);
    lin[t] = s;
    __syncthreads();
    if (t < DIM)
        g_hgate[m * DIM + t] = 0.5f * lin[t] / (1.0f + expf(-lin[t + DIM]));
}

// ---------------- argmax + fused output (warp per row) -----------------------
__global__ __launch_bounds__(256) void k_out(const float* __restrict__ x,
                                             float* __restrict__ out) {
    int tid = threadIdx.x, w = tid >> 5, lane = tid & 31;
    float cl[8];
#pragma unroll
    for (int i = 0; i < 8; i++) cl[i] = g_C[3][lane * 8 + i];
    int row0 = blockIdx.x * 64 + w * 8;
    for (int r = 0; r < 8; r++) {
        int row = row0 + r;
        const float4* p = (const float4*)&g_E[(size_t)row * KC + lane * 8];
        float4 e0 = p[0], e1 = p[1];
        float e[8] = {e0.x, e0.y, e0.z, e0.w, e1.x, e1.y, e1.z, e1.w};
        // lanes 0-15 cover cols 0..127 (local), 16-31 cover 128..255 (global)
        float best = -1.0f; int bi = lane * 8;
#pragma unroll
        for (int i = 0; i < 8; i++) {
            float v = e[i] * cl[i];
            if (v > best) { best = v; bi = lane * 8 + i; }   // first-max wins
        }
#pragma unroll
        for (int o = 8; o; o >>= 1) {  // butterfly within each 16-lane half
            float ov = __shfl_xor_sync(0xffffffffu, best, o);
            int   oi = __shfl_xor_sync(0xffffffffu, bi, o);
            if (ov > best || (ov == best && oi < bi)) { best = ov; bi = oi; }
        }
        int la = __shfl_sync(0xffffffffu, bi, 0);
        int ga = __shfl_sync(0xffffffffu, bi, 16) - MPROT;
        if (lane == 0) atomicMax(&g_lastIdx[la], row);

        const float* hg = g_hgate + (size_t)ga * DIM;
        const float* xr = x + (size_t)row * DIM;
        float o6[6]; float ssq = 0.f;
#pragma unroll
        for (int k = 0; k < 6; k++) {
            int c = lane + 32 * k;
            float v = hg[c] + 0.5f * xr[c];
            o6[k] = v; ssq += v * v;
        }
#pragma unroll
        for (int o = 16; o; o >>= 1) ssq += __shfl_xor_sync(0xffffffffu, ssq, o);
        float inv = rsqrtf(fmaxf(ssq, 1e-12f));
        float* orow = out + (size_t)row * DIM;
#pragma unroll
        for (int k = 0; k < 6; k++) orow[lane + 32 * k] = o6[k] * inv;
    }
}

// ---------------- EMA-updated local prototypes (last-write-wins) -------------
__global__ void k_newlocal(const float* __restrict__ lp, const float* __restrict__ x,
                           float* __restrict__ out) {
    int e = blockIdx.x * 256 + threadIdx.x;   // 24576 elements
    int m = e / DIM, d = e % DIM;
    int i = g_lastIdx[m];
    float v = (i < 0) ? lp[e] : 0.96f * lp[e] + 0.04f * x[(size_t)i * DIM + d];
    out[(size_t)NROWS * DIM + e] = v;
}

// ---------------- launch ------------------------------------------------------
extern "C" void kernel_launch(void* const* d_in, const int* in_sizes, int n_in,
                              void* d_out, int out_size) {
    const float* x  = (const float*)d_in[0];  // projections [128,1024,192]
    const float* lp = (const float*)d_in[1];  // localPrototypes [128,192]
    const float* gp = (const float*)d_in[2];  // globalPrototypes [128,192]
    const float* W  = (const float*)d_in[3];  // glu_W [192,384]
    const float* b  = (const float*)d_in[4];  // glu_b [384]
    float* out = (float*)d_out;               // [normed | new_local]

    k_init<<<1, 256>>>();
    k_protos<<<1, 256>>>(lp, gp);
    k_gemm<<<NROWS / 64, 256>>>(x);  // sim, E, row norms, colsum[0] (fused)
    k_setC<<<1, 256>>>(0);           // C1
    k_pass<<<NROWS / 64, 256>>>(1);  // -> colsum[1]
    k_setC<<<1, 256>>>(1);           // C2
    k_pass<<<NROWS / 64, 256>>>(2);  // -> colsum[2]
    k_setC<<<1, 256>>>(2);           // C3
    k_glu<<<MPROT, 2 * DIM>>>(gp, W, b);
    k_out<<<NROWS / 64, 256>>>(x, out);
    k_newlocal<<<MPROT * DIM / 256, 256>>>(lp, x, out);
}

// round 15
// speedup vs baseline: 1.0355x; 1.0355x over previous
#include <cuda_runtime.h>
#include <cstdint>

#define NROWS 131072
#define DIM   192
#define KC    256     // concat(local, global) prototype count
#define MPROT 128
#define INV_T 20.0f   // 1 / 0.05

// ---------------- device scratch (allocation-free: module globals) ----------
__device__ float  g_E[(size_t)NROWS * KC];   // exp(sim/T), 128 MB
__device__ float  g_pnT[DIM * KC];           // normalized protos, transposed [k][j]
__device__ double g_colsum[3][KC];           // sinkhorn colsum accumulators
__device__ float  g_C[4][KC];                // column factors (C[1..3] used)
__device__ float  g_hgate[MPROT * DIM];      // 0.5 * GLU(globalProto) table
__device__ int    g_lastIdx[MPROT];          // last row assigned per local proto

// ---------------- init: zero accumulators every launch ----------------------
__global__ void k_init() {
    int t = threadIdx.x;
    if (t < MPROT) g_lastIdx[t] = -1;
    for (int i = t; i < 3 * KC; i += blockDim.x)
        ((double*)g_colsum)[i] = 0.0;
}

// ---------------- normalize prototypes, store transposed --------------------
__global__ void k_protos(const float* __restrict__ lp, const float* __restrict__ gp) {
    int j = threadIdx.x;  // 0..255
    const float* src = (j < MPROT) ? (lp + j * DIM) : (gp + (j - MPROT) * DIM);
    float ss = 0.f;
    for (int k = 0; k < DIM; k++) { float v = src[k]; ss += v * v; }
    float inv = rsqrtf(fmaxf(ss, 1e-12f));
    for (int k = 0; k < DIM; k++) g_pnT[k * KC + j] = src[k] * inv;
}

// ---------------- GEMM: sim = x @ pnT, E = exp(sim * invx * 20) -------------
// Block: 64 rows x 256 cols, 256 threads. Thread tile 8 rows x 8 cols.
// Crossbar-debottlenecked: a read as LDS.128 broadcast (2 adjacent {a,a}
// pairs, k stepped by 2) -> per warp-k phases: b 8 + a 4 = 12 < fma 16.
// Row ||x||^2 fused into the A-load phase. Epilogue = sinkhorn iteration 0.
__global__ __launch_bounds__(256, 2) void k_gemm(const float* __restrict__ x) {
    __shared__ unsigned long long As2[64][32];   // {a,a} pairs, 16 KB
    __shared__ float Bs[32][KC];                 // 32 KB (reused for reduction)
    __shared__ float normp[64][8];               // ||x||^2 partials
    __shared__ float sinvx[64];                  // 1/||x|| per row
    int rowBase = blockIdx.x * 64;
    int tid = threadIdx.x;
    int ty = tid >> 5;   // warp -> 8-row group (a loads are warp-uniform)
    int tx = tid & 31;   // lane -> column pairs

    unsigned long long acc[8][4];
#pragma unroll
    for (int i = 0; i < 8; i++)
#pragma unroll
        for (int j = 0; j < 4; j++) acc[i][j] = 0ull;

    int ar = tid >> 3;         // A row (0..31); +32 for second half
    int ac = (tid & 7) * 4;    // A col within chunk
    float ss0 = 0.f, ss1 = 0.f;

    for (int kb = 0; kb < DIM; kb += 32) {
        // A tile 64x32 as duplicated u64 pairs; accumulate ||x||^2 partials
#pragma unroll
        for (int u = 0; u < 2; u++) {
            int r = ar + u * 32;
            float4 v = *(const float4*)&x[(size_t)(rowBase + r) * DIM + kb + ac];
            float d = v.x * v.x + v.y * v.y + v.z * v.z + v.w * v.w;
            if (u == 0) ss0 += d; else ss1 += d;
            unsigned long long p0, p1, p2, p3;
            asm("mov.b64 %0, {%1, %1};" : "=l"(p0) : "f"(v.x));
            asm("mov.b64 %0, {%1, %1};" : "=l"(p1) : "f"(v.y));
            asm("mov.b64 %0, {%1, %1};" : "=l"(p2) : "f"(v.z));
            asm("mov.b64 %0, {%1, %1};" : "=l"(p3) : "f"(v.w));
            As2[r][ac + 0] = p0; As2[r][ac + 1] = p1;
            As2[r][ac + 2] = p2; As2[r][ac + 3] = p3;
        }
        // B tile 32x256: 2048 float4, 8 per thread (coalesced, conflict-free)
#pragma unroll
        for (int u = 0; u < 8; u++) {
            int f = tid + u * 256;
            int kk = f >> 6, c = (f & 63) * 4;
            *(float4*)&Bs[kk][c] = *(const float4*)&g_pnT[(kb + kk) * KC + c];
        }
        __syncthreads();
#pragma unroll
        for (int k = 0; k < 32; k += 2) {
            unsigned long long b0[4], b1[4];
#pragma unroll
            for (int j = 0; j < 4; j++) {
                b0[j] = *(const unsigned long long*)&Bs[k][64 * j + 2 * tx];
                b1[j] = *(const unsigned long long*)&Bs[k + 1][64 * j + 2 * tx];
            }
#pragma unroll
            for (int i = 0; i < 8; i++) {
                // LDS.128 broadcast: {a,a} pairs for k and k+1 (16B aligned)
                ulonglong2 av = *(const ulonglong2*)&As2[ty * 8 + i][k];
#pragma unroll
                for (int j = 0; j < 4; j++) {
                    asm("fma.rn.f32x2 %0, %1, %2, %0;"
                        : "+l"(acc[i][j]) : "l"(av.x), "l"(b0[j]));
                    asm("fma.rn.f32x2 %0, %1, %2, %0;"
                        : "+l"(acc[i][j]) : "l"(av.y), "l"(b1[j]));
                }
            }
        }
        __syncthreads();
    }

    // finalize 1/||x|| per row (8 partials per row)
    normp[ar][tid & 7] = ss0;
    normp[ar + 32][tid & 7] = ss1;
    __syncthreads();
    if (tid < 64) {
        float s = 0.f;
#pragma unroll
        for (int j = 0; j < 8; j++) s += normp[tid][j];
        sinvx[tid] = rsqrtf(fmaxf(s, 1e-12f));
    }
    __syncthreads();

    // epilogue: E = exp(20*sim/||x||), store E, accumulate colsum[0] += E/rowsum
    float colAcc[8] = {0, 0, 0, 0, 0, 0, 0, 0};
#pragma unroll
    for (int i = 0; i < 8; i++) {
        int row = rowBase + ty * 8 + i;
        float sc = INV_T * sinvx[ty * 8 + i];
        float ev[8];
        float rsum = 0.f;
#pragma unroll
        for (int j = 0; j < 4; j++) {
            float lo, hi;
            asm("mov.b64 {%0, %1}, %2;" : "=f"(lo), "=f"(hi) : "l"(acc[i][j]));
            float e0 = __expf(sc * lo);
            float e1 = __expf(sc * hi);
            ev[2 * j] = e0; ev[2 * j + 1] = e1;
            rsum += e0 + e1;
            int c = 64 * j + 2 * tx;
            *(float2*)&g_E[(size_t)row * KC + c] = make_float2(e0, e1);
        }
#pragma unroll
        for (int o = 16; o; o >>= 1) rsum += __shfl_xor_sync(0xffffffffu, rsum, o);
        float R = 1.0f / rsum;   // warp holds the full row -> exact rowsum
#pragma unroll
        for (int j = 0; j < 8; j++) colAcc[j] = fmaf(ev[j], R, colAcc[j]);
    }

    // block-reduce colAcc into g_colsum[0] (reuse Bs: mainloop done with it)
    double (*wsum)[KC] = (double(*)[KC])Bs;
#pragma unroll
    for (int j = 0; j < 4; j++) {
        wsum[ty][64 * j + 2 * tx]     = (double)colAcc[2 * j];
        wsum[ty][64 * j + 2 * tx + 1] = (double)colAcc[2 * j + 1];
    }
    __syncthreads();
    double s = 0.0;
#pragma unroll
    for (int ww = 0; ww < 8; ww++) s += wsum[ww][tid];
    atomicAdd(&g_colsum[0][tid], s);
}

// ---------------- finalize column factors: C[t+1][j] = 1/(256*colsum[t][j]) --
__global__ void k_setC(int t) {
    int j = threadIdx.x;
    g_C[t + 1][j] = (float)(1.0 / (256.0 * g_colsum[t][j]));
}

// ---------------- one sinkhorn iteration: one pass over E --------------------
// R_i = 1/(N * sum_j E_ij C_j);  colsum_j += sum_i E_ij R_i   (double accum)
// Loads front-batched (16 independent LDG.128 -> MLP 16) before reductions.
__global__ __launch_bounds__(256) void k_pass(int iter) {
    __shared__ double wsum[8][KC];
    int tid = threadIdx.x, w = tid >> 5, lane = tid & 31;
    const float* C = g_C[iter];
    float cl[8];
#pragma unroll
    for (int i = 0; i < 8; i++) cl[i] = C[lane * 8 + i];
    int row0 = blockIdx.x * 64 + w * 8;

    float4 eb[16];
#pragma unroll
    for (int r = 0; r < 8; r++) {
        const float4* p = (const float4*)&g_E[(size_t)(row0 + r) * KC + lane * 8];
        eb[2 * r] = p[0]; eb[2 * r + 1] = p[1];
    }

    float colAcc[8] = {0, 0, 0, 0, 0, 0, 0, 0};
#pragma unroll
    for (int r = 0; r < 8; r++) {
        float e[8] = {eb[2 * r].x, eb[2 * r].y, eb[2 * r].z, eb[2 * r].w,
                      eb[2 * r + 1].x, eb[2 * r + 1].y, eb[2 * r + 1].z, eb[2 * r + 1].w};
        float rd = 0.f;
#pragma unroll
        for (int i = 0; i < 8; i++) rd = fmaf(e[i], cl[i], rd);
#pragma unroll
        for (int o = 16; o; o >>= 1) rd += __shfl_xor_sync(0xffffffffu, rd, o);
        float R = 1.0f / (131072.0f * rd);
#pragma unroll
        for (int i = 0; i < 8; i++) colAcc[i] = fmaf(e[i], R, colAcc[i]);
    }
#pragma unroll
    for (int i = 0; i < 8; i++) wsum[w][lane * 8 + i] = (double)colAcc[i];
    __syncthreads();
    double s = 0.0;
#pragma unroll
    for (int ww = 0; ww < 8; ww++) s += wsum[ww][tid];
    atomicAdd(&g_colsum[iter][tid], s);
}

// ---------------- 0.5*GLU table for the 128 global prototypes ----------------
__global__ void k_glu(const float* __restrict__ gp, const float* __restrict__ W,
                      const float* __restrict__ bias) {
    __shared__ float gpr[DIM];
    __shared__ float lin[2 * DIM];
    int m = blockIdx.x, t = threadIdx.x;     // 384 threads
    if (t < DIM) gpr[t] = gp[m * DIM + t];
    __syncthreads();
    float s = bias[t];
    for (int k = 0; k < DIM; k++) s = fmaf(gpr[k], W[(size_t)k * 2 * DIM + t], s);
    lin[t] = s;
    __syncthreads();
    if (t < DIM)
        g_hgate[m * DIM + t] = 0.5f * lin[t] / (1.0f + expf(-lin[t + DIM]));
}

// ---------------- argmax + fused output (warp per row) -----------------------
__global__ __launch_bounds__(256) void k_out(const float* __restrict__ x,
                                             float* __restrict__ out) {
    int tid = threadIdx.x, w = tid >> 5, lane = tid & 31;
    float cl[8];
#pragma unroll
    for (int i = 0; i < 8; i++) cl[i] = g_C[3][lane * 8 + i];
    int row0 = blockIdx.x * 64 + w * 8;
    for (int r = 0; r < 8; r++) {
        int row = row0 + r;
        const float4* p = (const float4*)&g_E[(size_t)row * KC + lane * 8];
        float4 e0 = p[0], e1 = p[1];
        float e[8] = {e0.x, e0.y, e0.z, e0.w, e1.x, e1.y, e1.z, e1.w};
        // lanes 0-15 cover cols 0..127 (local), 16-31 cover 128..255 (global)
        float best = -1.0f; int bi = lane * 8;
#pragma unroll
        for (int i = 0; i < 8; i++) {
            float v = e[i] * cl[i];
            if (v > best) { best = v; bi = lane * 8 + i; }   // first-max wins
        }
#pragma unroll
        for (int o = 8; o; o >>= 1) {  // butterfly within each 16-lane half
            float ov = __shfl_xor_sync(0xffffffffu, best, o);
            int   oi = __shfl_xor_sync(0xffffffffu, bi, o);
            if (ov > best || (ov == best && oi < bi)) { best = ov; bi = oi; }
        }
        int la = __shfl_sync(0xffffffffu, bi, 0);
        int ga = __shfl_sync(0xffffffffu, bi, 16) - MPROT;
        if (lane == 0) atomicMax(&g_lastIdx[la], row);

        const float* hg = g_hgate + (size_t)ga * DIM;
        const float* xr = x + (size_t)row * DIM;
        float o6[6]; float ssq = 0.f;
#pragma unroll
        for (int k = 0; k < 6; k++) {
            int c = lane + 32 * k;
            float v = hg[c] + 0.5f * xr[c];
            o6[k] = v; ssq += v * v;
        }
#pragma unroll
        for (int o = 16; o; o >>= 1) ssq += __shfl_xor_sync(0xffffffffu, ssq, o);
        float inv = rsqrtf(fmaxf(ssq, 1e-12f));
        float* orow = out + (size_t)row * DIM;
#pragma unroll
        for (int k = 0; k < 6; k++) orow[lane + 32 * k] = o6[k] * inv;
    }
}

// ---------------- EMA-updated local prototypes (last-write-wins) -------------
__global__ void k_newlocal(const float* __restrict__ lp, const float* __restrict__ x,
                           float* __restrict__ out) {
    int e = blockIdx.x * 256 + threadIdx.x;   // 24576 elements
    int m = e / DIM, d = e % DIM;
    int i = g_lastIdx[m];
    float v = (i < 0) ? lp[e] : 0.96f * lp[e] + 0.04f * x[(size_t)i * DIM + d];
    out[(size_t)NROWS * DIM + e] = v;
}

// ---------------- launch ------------------------------------------------------
// NOTE: k_glu launched FIRST (it is independent) so that ncu's fixed
// "-s 5 -c 1" capture lands on k_pass(1) instead of k_setC.
extern "C" void kernel_launch(void* const* d_in, const int* in_sizes, int n_in,
                              void* d_out, int out_size) {
    const float* x  = (const float*)d_in[0];  // projections [128,1024,192]
    const float* lp = (const float*)d_in[1];  // localPrototypes [128,192]
    const float* gp = (const float*)d_in[2];  // globalPrototypes [128,192]
    const float* W  = (const float*)d_in[3];  // glu_W [192,384]
    const float* b  = (const float*)d_in[4];  // glu_b [384]
    float* out = (float*)d_out;               // [normed | new_local]

    k_glu<<<MPROT, 2 * DIM>>>(gp, W, b);      // idx 0 (independent)
    k_init<<<1, 256>>>();                     // idx 1
    k_protos<<<1, 256>>>(lp, gp);             // idx 2
    k_gemm<<<NROWS / 64, 256>>>(x);           // idx 3: sim, E, norms, colsum[0]
    k_setC<<<1, 256>>>(0);                    // idx 4: C1
    k_pass<<<NROWS / 64, 256>>>(1);           // idx 5: profiled by ncu
    k_setC<<<1, 256>>>(1);                    // C2
    k_pass<<<NROWS / 64, 256>>>(2);           // -> colsum[2]
    k_setC<<<1, 256>>>(2);                    // C3
    k_out<<<NROWS / 64, 256>>>(x, out);
    k_newlocal<<<MPROT * DIM / 256, 256>>>(lp, x, out);
}